// round 4
// baseline (speedup 1.0000x reference)
#include <cuda_runtime.h>

#define NB 8
#define NT 4095
#define NS 2048
#define ND 300
#define ND4 75            // ND / 4
#define PAD_IDX 1
#define NCHUNK 256
#define CLEN 8            // NS / NCHUNK

// ---- scratch (static __device__, no allocations) ----
__device__ __align__(16) int   g_leaves[NB * NS];
__device__ __align__(16) float g_prefix[(long)NB * (NS + 1) * ND];  // exclusive prefix, ~19.7 MB
__device__ __align__(16) float g_csum[NB * NCHUNK * ND];

// ---------------------------------------------------------------------------
// 1) Pack leaves: left-pack tokens with (lo==hi && tok!=PAD) per batch.
//    One block (1024 threads) per batch; ballot-based block scan, 4 tiles.
// ---------------------------------------------------------------------------
__global__ void pack_kernel(const int* __restrict__ x, const int2* __restrict__ idx) {
    const int b = blockIdx.x;
    const int tid = threadIdx.x;
    const int lane = tid & 31;
    const int w = tid >> 5;
    __shared__ int warp_sums[32];
    __shared__ int s_base;
    if (tid == 0) s_base = 0;
    __syncthreads();

    #pragma unroll
    for (int start = 0; start < 4096; start += 1024) {
        int t = start + tid;
        int flag = 0;
        int tok = PAD_IDX;
        if (t < NT) {
            tok = x[b * NT + t];
            int2 lh = idx[b * NT + t];
            flag = (lh.x == lh.y && tok != PAD_IDX) ? 1 : 0;
        }
        unsigned m = __ballot_sync(0xffffffffu, flag);
        int within = __popc(m & ((1u << lane) - 1u));
        if (lane == 0) warp_sums[w] = __popc(m);
        __syncthreads();
        int woff = 0, tot = 0;
        #pragma unroll
        for (int i = 0; i < 32; i++) {
            int ws = warp_sums[i];
            if (i < w) woff += ws;
            tot += ws;
        }
        int pos = s_base + woff + within;
        if (flag && pos < NS) g_leaves[b * NS + pos] = tok;
        __syncthreads();
        if (tid == 0) s_base += tot;
        __syncthreads();
    }
    // fill unfilled tail with PAD (W[PAD] row is zero)
    for (int p = s_base + tid; p < NS; p += 1024) g_leaves[b * NS + p] = PAD_IDX;
}

// ---------------------------------------------------------------------------
// 2a) Chunk sums (float4 over d): g_csum[b][c][:] = sum_{r in chunk} W[leaf]
//     grid (NCHUNK/4, NB), block (75, 4): ty selects chunk, tx = float4 lane.
// ---------------------------------------------------------------------------
__global__ __launch_bounds__(300) void chunksum_kernel(const float4* __restrict__ W4) {
    const int c = blockIdx.x * 4 + threadIdx.y;
    const int b = blockIdx.y;
    const int j = threadIdx.x;                 // 0..74
    const int4* lv = (const int4*)&g_leaves[b * NS + c * CLEN];
    int4 l0 = lv[0], l1 = lv[1];

    float4 v0 = __ldg(&W4[(long)l0.x * ND4 + j]);
    float4 v1 = __ldg(&W4[(long)l0.y * ND4 + j]);
    float4 v2 = __ldg(&W4[(long)l0.z * ND4 + j]);
    float4 v3 = __ldg(&W4[(long)l0.w * ND4 + j]);
    float4 v4 = __ldg(&W4[(long)l1.x * ND4 + j]);
    float4 v5 = __ldg(&W4[(long)l1.y * ND4 + j]);
    float4 v6 = __ldg(&W4[(long)l1.z * ND4 + j]);
    float4 v7 = __ldg(&W4[(long)l1.w * ND4 + j]);

    float4 s;
    s.x = ((v0.x + v1.x) + (v2.x + v3.x)) + ((v4.x + v5.x) + (v6.x + v7.x));
    s.y = ((v0.y + v1.y) + (v2.y + v3.y)) + ((v4.y + v5.y) + (v6.y + v7.y));
    s.z = ((v0.z + v1.z) + (v2.z + v3.z)) + ((v4.z + v5.z) + (v6.z + v7.z));
    s.w = ((v0.w + v1.w) + (v2.w + v3.w)) + ((v4.w + v5.w) + (v6.w + v7.w));
    ((float4*)g_csum)[(b * NCHUNK + c) * ND4 + j] = s;
}

// ---------------------------------------------------------------------------
// 2b) Scan chunk sums in place -> exclusive chunk offsets.
//     One WARP per (b,d): lane holds chunks [8*lane, 8*lane+8), shfl scan.
// ---------------------------------------------------------------------------
__global__ void chunkscan_kernel() {
    int gw = (blockIdx.x * blockDim.x + threadIdx.x) >> 5;   // global warp id
    int lane = threadIdx.x & 31;
    if (gw >= NB * ND) return;
    int b = gw / ND, d = gw - b * ND;

    float* base = &g_csum[b * NCHUNK * ND + d];
    float v[8];
    float s = 0.f;
    #pragma unroll
    for (int r = 0; r < 8; r++) {
        v[r] = base[(8 * lane + r) * ND];
        s += v[r];
    }

    float incl = s;
    #pragma unroll
    for (int off = 1; off < 32; off <<= 1) {
        float n = __shfl_up_sync(0xffffffffu, incl, off);
        if (lane >= off) incl += n;
    }
    float acc = incl - s;   // exclusive base for this lane's 8 chunks
    #pragma unroll
    for (int r = 0; r < 8; r++) {
        base[(8 * lane + r) * ND] = acc;
        acc += v[r];
    }
}

// ---------------------------------------------------------------------------
// 2c) Exclusive prefix P[b][r][:] (float4 over d); last chunk writes P[b][S].
//     grid (NCHUNK/4, NB), block (75, 4).
// ---------------------------------------------------------------------------
__global__ __launch_bounds__(300) void prefix_kernel(const float4* __restrict__ W4) {
    const int c = blockIdx.x * 4 + threadIdx.y;
    const int b = blockIdx.y;
    const int j = threadIdx.x;                 // 0..74
    const int4* lv = (const int4*)&g_leaves[b * NS + c * CLEN];
    int4 l0 = lv[0], l1 = lv[1];

    float4 v0 = __ldg(&W4[(long)l0.x * ND4 + j]);
    float4 v1 = __ldg(&W4[(long)l0.y * ND4 + j]);
    float4 v2 = __ldg(&W4[(long)l0.z * ND4 + j]);
    float4 v3 = __ldg(&W4[(long)l0.w * ND4 + j]);
    float4 v4 = __ldg(&W4[(long)l1.x * ND4 + j]);
    float4 v5 = __ldg(&W4[(long)l1.y * ND4 + j]);
    float4 v6 = __ldg(&W4[(long)l1.z * ND4 + j]);
    float4 v7 = __ldg(&W4[(long)l1.w * ND4 + j]);

    float4 acc = ((const float4*)g_csum)[(b * NCHUNK + c) * ND4 + j];
    float4* P = &((float4*)g_prefix)[((long)b * (NS + 1) + (long)c * CLEN) * ND4 + j];

    P[0 * ND4] = acc;
    acc.x += v0.x; acc.y += v0.y; acc.z += v0.z; acc.w += v0.w;
    P[1 * ND4] = acc;
    acc.x += v1.x; acc.y += v1.y; acc.z += v1.z; acc.w += v1.w;
    P[2 * ND4] = acc;
    acc.x += v2.x; acc.y += v2.y; acc.z += v2.z; acc.w += v2.w;
    P[3 * ND4] = acc;
    acc.x += v3.x; acc.y += v3.y; acc.z += v3.z; acc.w += v3.w;
    P[4 * ND4] = acc;
    acc.x += v4.x; acc.y += v4.y; acc.z += v4.z; acc.w += v4.w;
    P[5 * ND4] = acc;
    acc.x += v5.x; acc.y += v5.y; acc.z += v5.z; acc.w += v5.w;
    P[6 * ND4] = acc;
    acc.x += v6.x; acc.y += v6.y; acc.z += v6.z; acc.w += v6.w;
    P[7 * ND4] = acc;
    acc.x += v7.x; acc.y += v7.y; acc.z += v7.z; acc.w += v7.w;
    if (c == NCHUNK - 1) P[(long)CLEN * ND4] = acc;   // P[b][S][:]
}

// ---------------------------------------------------------------------------
// 3) Query: out[b][t] = (P[hi+1] - P[lo]) / denom.  float4 over d.
// ---------------------------------------------------------------------------
__global__ void out_kernel(const int2* __restrict__ idxp, float4* __restrict__ out) {
    const float4* __restrict__ P4 = (const float4*)g_prefix;
    int i = blockIdx.x * blockDim.x + threadIdx.x;
    if (i >= NB * NT * ND4) return;
    int bt = i / ND4;
    int j = i - bt * ND4;
    int b = bt / NT;
    int2 lh = idxp[bt];
    int dn = lh.y - lh.x + 1;
    if (dn < 1) dn = 1;
    float inv = 1.0f / (float)dn;
    long base = (long)b * (NS + 1) * ND4;
    float4 a = __ldg(&P4[base + (long)(lh.y + 1) * ND4 + j]);
    float4 c = __ldg(&P4[base + (long)lh.x * ND4 + j]);
    float4 o;
    o.x = (a.x - c.x) * inv;
    o.y = (a.y - c.y) * inv;
    o.z = (a.z - c.z) * inv;
    o.w = (a.w - c.w) * inv;
    out[i] = o;
}

// ---------------------------------------------------------------------------
extern "C" void kernel_launch(void* const* d_in, const int* in_sizes, int n_in,
                              void* d_out, int out_size) {
    const int*  x   = (const int*)d_in[0];      // [B,T]   int32
    const int2* idx = (const int2*)d_in[1];     // [B,T,2] int32
    const float4* W4 = (const float4*)d_in[2];  // [V,D]   fp32
    float* out = (float*)d_out;                 // [B,T,D] fp32

    pack_kernel<<<NB, 1024>>>(x, idx);

    dim3 blk(75, 4);
    dim3 gscan(NCHUNK / 4, NB);                 // 64 x 8 = 512 blocks
    chunksum_kernel<<<gscan, blk>>>(W4);

    int nwarp = NB * ND;                         // 2400 warps
    chunkscan_kernel<<<(nwarp * 32 + 255) / 256, 256>>>();

    prefix_kernel<<<gscan, blk>>>(W4);

    int n4 = NB * NT * ND4;
    out_kernel<<<(n4 + 255) / 256, 256>>>(idx, (float4*)out);
}